// round 8
// baseline (speedup 1.0000x reference)
#include <cuda_runtime.h>

#define PH 7
#define PW 7
#define G  7
#define D  8
#define C  (D * G * G)      // 392
#define NB 4
#define H  96
#define W  96
#define R  512
#define SCALEF 0.0625f
#define OUT_PER_ROI (D * PH * PW)   // 392
#define MAXEXT 6
#define TPB2 256
#define NGROUP (TPB2 / 4)   // 64 groups of 4 lanes

// precomputed per-roi geometry (kernel 1 -> kernel 2)
__device__ int   g_gh[R * PH];      // hs | he<<8
__device__ int   g_gw[R * PW];      // ws | we<<8
__device__ float g_invh[R * PH];
__device__ float g_invw[R * PW];
__device__ int   g_list[NB][R];     // roi indices per batch
__device__ int   g_cnt[NB];

// ---------------- kernel 1: geometry + batch lists (1 block, 512 thr) -------
__global__ __launch_bounds__(R) void psroi_setup(const float* __restrict__ rois)
{
    const int t = threadIdx.x;     // == roi index, R == 512
    __shared__ int s_cnt[NB];
    if (t < NB) s_cnt[t] = 0;
    __syncthreads();

    const float* rp = rois + (size_t)t * 5;
    const int   b  = (int)rp[0];
    float x1 = __fmul_rn(rintf(rp[1]), SCALEF);
    float y1 = __fmul_rn(rintf(rp[2]), SCALEF);
    float x2 = __fmul_rn(rintf(__fadd_rn(rp[3], 1.0f)), SCALEF);
    float y2 = __fmul_rn(rintf(__fadd_rn(rp[4], 1.0f)), SCALEF);
    float rw = fmaxf(__fsub_rn(x2, x1), 0.1f);
    float rh = fmaxf(__fsub_rn(y2, y1), 0.1f);
    float bsw = __fdiv_rn(rw, (float)PW);
    float bsh = __fdiv_rn(rh, (float)PH);

    #pragma unroll
    for (int p = 0; p < PH; ++p) {
        float sv = fminf(fmaxf(floorf(__fadd_rn(__fmul_rn((float)p,       bsh), y1)), 0.0f), (float)H);
        float ev = fminf(fmaxf(ceilf (__fadd_rn(__fmul_rn((float)(p + 1), bsh), y1)), 0.0f), (float)H);
        g_gh[t * PH + p]   = ((int)sv) | (((int)ev) << 8);
        g_invh[t * PH + p] = 1.0f / fmaxf(fmaxf(__fsub_rn(ev, sv), 0.0f), 1.0f);
    }
    #pragma unroll
    for (int q = 0; q < PW; ++q) {
        float sv = fminf(fmaxf(floorf(__fadd_rn(__fmul_rn((float)q,       bsw), x1)), 0.0f), (float)W);
        float ev = fminf(fmaxf(ceilf (__fadd_rn(__fmul_rn((float)(q + 1), bsw), x1)), 0.0f), (float)W);
        g_gw[t * PW + q]   = ((int)sv) | (((int)ev) << 8);
        g_invw[t * PW + q] = 1.0f / fmaxf(fmaxf(__fsub_rn(ev, sv), 0.0f), 1.0f);
    }

    const int slot = atomicAdd(&s_cnt[b], 1);
    g_list[b][slot] = t;
    __syncthreads();
    if (t < NB) g_cnt[t] = s_cnt[t];
}

// ---------------- kernel 2: stream plane -> smem, gather bins ---------------
__global__ __launch_bounds__(TPB2) void psroi_main(
    const float* __restrict__ feat,   // [B, C, H, W]
    float* __restrict__ out)          // [R, D, PH, PW]
{
    const int c = blockIdx.x;          // channel (== d*49 + p*7 + q)
    const int b = blockIdx.y;
    const int t = threadIdx.x;

    const int q = c % PW;
    const int p = (c / PW) % PH;

    __shared__ float s_plane[H * W];   // 36 KB

    // stream this (b, c) plane, fully coalesced, 9 float4 per thread
    {
        const float4* src = (const float4*)(feat + ((size_t)b * C + c) * (H * W));
        float4* dst = (float4*)s_plane;
        #pragma unroll
        for (int i = 0; i < (H * W) / 4 / TPB2; ++i)
            dst[i * TPB2 + t] = src[i * TPB2 + t];
    }
    __syncthreads();

    const int cnt = g_cnt[b];
    const int g = t >> 2;              // group 0..63
    const int l = t & 3;               // lane covers cols l and l+4

    for (int base = 0; base < cnt; base += NGROUP) {
        const int idx = base + g;
        if (idx < cnt) {
            const int r  = g_list[b][idx];
            const int gh = g_gh[r * PH + p];
            const int gw = g_gw[r * PW + q];
            const float inv = g_invh[r * PH + p] * g_invw[r * PW + q];

            const int hs = gh & 0xff, eh = (gh >> 8) - hs;
            const int ws = gw & 0xff, ew = (gw >> 8) - ws;

            const float* bp = s_plane + hs * W + ws;
            const bool ok0 = (l     < ew);
            const bool ok1 = (l + 4 < ew);

            float v = 0.0f;
            #pragma unroll
            for (int k = 0; k < MAXEXT; ++k) {
                if (k < eh) {
                    float a  = ok0 ? bp[k * W + l]     : 0.0f;
                    float bb = ok1 ? bp[k * W + l + 4] : 0.0f;
                    v += a + bb;
                }
            }

            v += __shfl_xor_sync(0xffffffffu, v, 2);
            v += __shfl_xor_sync(0xffffffffu, v, 1);

            if (l == 0) {
                out[(size_t)r * OUT_PER_ROI + c] = v * inv;
            }
        }
    }
}

extern "C" void kernel_launch(void* const* d_in, const int* in_sizes, int n_in,
                              void* d_out, int out_size)
{
    const float* feat = (const float*)d_in[0];
    const float* rois = (const float*)d_in[1];
    float* out        = (float*)d_out;

    psroi_setup<<<1, R>>>(rois);
    dim3 grid(C, NB);                  // (392, 4)
    psroi_main<<<grid, TPB2>>>(feat, out);
}

// round 9
// speedup vs baseline: 1.5572x; 1.5572x over previous
#include <cuda_runtime.h>

#define PH 7
#define PW 7
#define G  7
#define D  8
#define C  (D * G * G)      // 392
#define NB 4
#define H  96
#define W  96
#define R  512
#define SCALEF 0.0625f
#define OUT_PER_ROI (D * PH * PW)   // 392
#define TPB 256
#define RPB 256                      // rois per block
#define NGROUP (TPB / 4)             // 64 groups of 4 lanes

__global__ __launch_bounds__(TPB, 8) void psroi_kernel(
    const float* __restrict__ feat,   // [B, C, H, W]
    const float* __restrict__ rois,   // [R, 5]
    float* __restrict__ out)          // [R, D, PH, PW]
{
    const int c  = blockIdx.x;             // channel == d*49 + p*7 + q
    const int r0 = blockIdx.y * RPB;
    const int t  = threadIdx.x;

    const int q = c % PW;
    const int p = (c / PW) % PH;

    __shared__ int   s_off[RPB];     // feat base offset for this bin
    __shared__ int   s_ext[RPB];     // eh | ew<<8
    __shared__ float s_inv[RPB];     // invh*invw
    __shared__ short s_list[3][RPB]; // class-S / M / L roi-local indices
    __shared__ int   s_cnt[3];

    if (t < 3) s_cnt[t] = 0;
    __syncthreads();

    // ---- phase 1: geometry + classification, one roi per thread
    {
        const int r = r0 + t;
        const float* rp = rois + (size_t)r * 5;
        const int b = (int)rp[0];
        float x1 = __fmul_rn(rintf(rp[1]), SCALEF);
        float y1 = __fmul_rn(rintf(rp[2]), SCALEF);
        float x2 = __fmul_rn(rintf(__fadd_rn(rp[3], 1.0f)), SCALEF);
        float y2 = __fmul_rn(rintf(__fadd_rn(rp[4], 1.0f)), SCALEF);
        float rw = fmaxf(__fsub_rn(x2, x1), 0.1f);
        float rh = fmaxf(__fsub_rn(y2, y1), 0.1f);
        float bsw = __fdiv_rn(rw, (float)PW);
        float bsh = __fdiv_rn(rh, (float)PH);

        float hsf = fminf(fmaxf(floorf(__fadd_rn(__fmul_rn((float)p,       bsh), y1)), 0.0f), (float)H);
        float hef = fminf(fmaxf(ceilf (__fadd_rn(__fmul_rn((float)(p + 1), bsh), y1)), 0.0f), (float)H);
        float wsf = fminf(fmaxf(floorf(__fadd_rn(__fmul_rn((float)q,       bsw), x1)), 0.0f), (float)W);
        float wef = fminf(fmaxf(ceilf (__fadd_rn(__fmul_rn((float)(q + 1), bsw), x1)), 0.0f), (float)W);

        const int hs = (int)hsf, he = (int)hef;
        const int ws = (int)wsf, we = (int)wef;
        const int eh = he - hs, ew = we - ws;

        s_off[t] = (b * C + c) * (H * W) + hs * W + ws;
        s_ext[t] = eh | (ew << 8);
        float nh = fmaxf(__fsub_rn(hef, hsf), 0.0f);
        float nw = fmaxf(__fsub_rn(wef, wsf), 0.0f);
        s_inv[t] = (1.0f / fmaxf(nh, 1.0f)) * (1.0f / fmaxf(nw, 1.0f));

        const int cls = (ew <= 4) ? ((eh <= 3) ? 0 : 1) : 2;
        const int slot = atomicAdd(&s_cnt[cls], 1);
        s_list[cls][slot] = (short)t;
    }
    __syncthreads();

    const int g = t >> 2;      // group 0..63
    const int l = t & 3;       // lane -> column offset

    const int cntS = s_cnt[0], cntM = s_cnt[1], cntL = s_cnt[2];

    // ---- class S: eh<=3, ew<=4 -> 3 loads (col l only)
    for (int i = g; i < cntS; i += NGROUP) {
        const int j = s_list[0][i];
        const int ext = s_ext[j];
        const int eh = ext & 0xff, ew = ext >> 8;
        const float* bp = feat + s_off[j] + l;
        const bool ok = (l < ew);

        float v = (ok && 0 < eh ? __ldg(bp)         : 0.0f)
                + (ok && 1 < eh ? __ldg(bp + W)     : 0.0f)
                + (ok && 2 < eh ? __ldg(bp + 2 * W) : 0.0f);

        v += __shfl_xor_sync(0xffffffffu, v, 2);
        v += __shfl_xor_sync(0xffffffffu, v, 1);
        if (l == 0) out[(size_t)(r0 + j) * OUT_PER_ROI + c] = v * s_inv[j];
    }

    // ---- class M: ew<=4 -> 6 loads (col l only)
    for (int i = g; i < cntM; i += NGROUP) {
        const int j = s_list[1][i];
        const int ext = s_ext[j];
        const int eh = ext & 0xff, ew = ext >> 8;
        const float* bp = feat + s_off[j] + l;
        const bool ok = (l < ew);

        float v = 0.0f;
        #pragma unroll
        for (int k = 0; k < 6; ++k)
            v += (ok && k < eh) ? __ldg(bp + k * W) : 0.0f;

        v += __shfl_xor_sync(0xffffffffu, v, 2);
        v += __shfl_xor_sync(0xffffffffu, v, 1);
        if (l == 0) out[(size_t)(r0 + j) * OUT_PER_ROI + c] = v * s_inv[j];
    }

    // ---- class L: ew 5..6 -> 12 loads (cols l and l+4)
    for (int i = g; i < cntL; i += NGROUP) {
        const int j = s_list[2][i];
        const int ext = s_ext[j];
        const int eh = ext & 0xff, ew = ext >> 8;
        const float* bp = feat + s_off[j] + l;
        const bool ok1 = (l + 4 < ew);   // l < ew always true here (ew >= 5 > 3)

        float v = 0.0f;
        #pragma unroll
        for (int k = 0; k < 6; ++k) {
            if (k < eh) {
                v += __ldg(bp + k * W);
                v += ok1 ? __ldg(bp + k * W + 4) : 0.0f;
            }
        }

        v += __shfl_xor_sync(0xffffffffu, v, 2);
        v += __shfl_xor_sync(0xffffffffu, v, 1);
        if (l == 0) out[(size_t)(r0 + j) * OUT_PER_ROI + c] = v * s_inv[j];
    }
}

extern "C" void kernel_launch(void* const* d_in, const int* in_sizes, int n_in,
                              void* d_out, int out_size)
{
    const float* feat = (const float*)d_in[0];
    const float* rois = (const float*)d_in[1];
    float* out        = (float*)d_out;

    dim3 grid(C, R / RPB);   // (392, 2) -> 784 blocks, single wave
    psroi_kernel<<<grid, TPB>>>(feat, rois, out);
}

// round 10
// speedup vs baseline: 2.1875x; 1.4048x over previous
#include <cuda_runtime.h>

#define PH 7
#define PW 7
#define G  7
#define D  8
#define C  (D * G * G)      // 392
#define NB 4
#define H  96
#define W  96
#define R  512
#define SCALEF 0.0625f
#define OUT_PER_ROI (D * PH * PW)   // 392
#define TPB 256
#define RPB 256
#define GRP 4
#define NGROUP (TPB / GRP)           // 64 groups
#define NPASS (RPB / NGROUP)         // 4 passes

__global__ __launch_bounds__(TPB, 6) void psroi_kernel(
    const float* __restrict__ feat,   // [B, C, H, W]
    const float* __restrict__ rois,   // [R, 5]
    float* __restrict__ out)          // [R, D, PH, PW]
{
    const int c  = blockIdx.x;             // channel == d*49 + p*7 + q
    const int r0 = blockIdx.y * RPB;
    const int t  = threadIdx.x;

    const int q = c % PW;
    const int p = (c / PW) % PH;

    // one int4 per roi-bin: {feat elem offset, eh|ew<<8, inv(float bits), out idx}
    __shared__ int4 s_pack[RPB];

    // ---- phase 1: geometry for THIS channel's (p,q), one roi per thread
    {
        const int r = r0 + t;
        const float* rp = rois + (size_t)r * 5;
        const int b = (int)rp[0];
        float x1 = __fmul_rn(rintf(rp[1]), SCALEF);
        float y1 = __fmul_rn(rintf(rp[2]), SCALEF);
        float x2 = __fmul_rn(rintf(__fadd_rn(rp[3], 1.0f)), SCALEF);
        float y2 = __fmul_rn(rintf(__fadd_rn(rp[4], 1.0f)), SCALEF);
        float rw = fmaxf(__fsub_rn(x2, x1), 0.1f);
        float rh = fmaxf(__fsub_rn(y2, y1), 0.1f);
        float bsw = __fdiv_rn(rw, (float)PW);
        float bsh = __fdiv_rn(rh, (float)PH);

        float hsf = fminf(fmaxf(floorf(__fadd_rn(__fmul_rn((float)p,       bsh), y1)), 0.0f), (float)H);
        float hef = fminf(fmaxf(ceilf (__fadd_rn(__fmul_rn((float)(p + 1), bsh), y1)), 0.0f), (float)H);
        float wsf = fminf(fmaxf(floorf(__fadd_rn(__fmul_rn((float)q,       bsw), x1)), 0.0f), (float)W);
        float wef = fminf(fmaxf(ceilf (__fadd_rn(__fmul_rn((float)(q + 1), bsw), x1)), 0.0f), (float)W);

        const int hs = (int)hsf;
        const int ws = (int)wsf;
        const int eh = (int)hef - hs;
        const int ew = (int)wef - ws;

        float nh = fmaxf(__fsub_rn(hef, hsf), 0.0f);
        float nw = fmaxf(__fsub_rn(wef, wsf), 0.0f);
        float inv = (1.0f / fmaxf(nh, 1.0f)) * (1.0f / fmaxf(nw, 1.0f));

        int4 pk;
        pk.x = (b * C + c) * (H * W) + hs * W + ws;   // fits 32-bit (< 14.5M)
        pk.y = eh | (ew << 8);
        pk.z = __float_as_int(inv);
        pk.w = r * OUT_PER_ROI + c;
        s_pack[t] = pk;
    }
    __syncthreads();

    // ---- phase 2: 4-lane groups, 4 fully-unrolled passes, 12 loads each
    const int g = t >> 2;      // group 0..63
    const int l = t & 3;       // lane -> cols l and l+4

    #pragma unroll
    for (int pass = 0; pass < NPASS; ++pass) {
        const int4 pk = s_pack[pass * NGROUP + g];

        const int eh = pk.y & 0xff;
        const int ew = pk.y >> 8;
        const float* bp = feat + pk.x + l;
        const bool ok0 = (l     < ew);
        const bool ok1 = (l + 4 < ew);

        float v = 0.0f;
        #pragma unroll
        for (int k = 0; k < 6; ++k) {
            float a  = (ok0 && k < eh) ? __ldg(bp + k * W)     : 0.0f;
            float b2 = (ok1 && k < eh) ? __ldg(bp + k * W + 4) : 0.0f;
            v += a + b2;
        }

        v += __shfl_xor_sync(0xffffffffu, v, 2);
        v += __shfl_xor_sync(0xffffffffu, v, 1);

        if (l == 0) {
            out[pk.w] = v * __int_as_float(pk.z);
        }
    }
}

extern "C" void kernel_launch(void* const* d_in, const int* in_sizes, int n_in,
                              void* d_out, int out_size)
{
    const float* feat = (const float*)d_in[0];
    const float* rois = (const float*)d_in[1];
    float* out        = (float*)d_out;

    dim3 grid(C, R / RPB);   // (392, 2) -> 784 blocks, single wave
    psroi_kernel<<<grid, TPB>>>(feat, rois, out);
}